// round 2
// baseline (speedup 1.0000x reference)
#include <cuda_runtime.h>
#include <math.h>

// Shapes fixed by the problem.
#define BB 2
#define SS 128
#define VV 1024
#define DD 512
#define KK 32

// Scratch for the collapsed first-layer weights (no device allocation allowed).
__device__ float g_weff[DD];
__device__ float g_c;

// ---------------------------------------------------------------------------
// Kernel 1: collapse the two linear layers.
//   w_eff[d] = sum_k W2[0,k] * W1[k,d];   c = b2[0] + sum_k b1[k]*W2[0,k]
// Tiny: 32x512 MACs, one block.
// ---------------------------------------------------------------------------
__global__ void weff_kernel(const float* __restrict__ W1,
                            const float* __restrict__ b1,
                            const float* __restrict__ W2,
                            const float* __restrict__ b2) {
    int d = blockIdx.x * blockDim.x + threadIdx.x;
    if (d < DD) {
        float s = 0.0f;
#pragma unroll
        for (int k = 0; k < KK; ++k) s += W2[k] * W1[k * DD + d];
        g_weff[d] = s;
    }
    if (d == 0) {
        float c = b2[0];
#pragma unroll
        for (int k = 0; k < KK; ++k) c += b1[k] * W2[k];
        g_c = c;
    }
}

// ---------------------------------------------------------------------------
// Kernel 2: per-(b,v) online-softmax attention over S, single pass over x.
// One CTA per (b,v). 256 threads; thread t owns d = {2t, 2t+1} (float2).
// Per chunk of 4 s-rows: loads -> dots -> warp shuffle reduce -> cross-warp
// smem reduce (double-buffered, 1 barrier) -> redundant online update in
// every thread (deterministic).
// ---------------------------------------------------------------------------
__global__ __launch_bounds__(256, 8)
void attn_kernel(const float* __restrict__ x, float* __restrict__ out) {
    const int bv  = blockIdx.x;          // 0..2047
    const int b   = bv >> 10;            // /1024
    const int v   = bv & (VV - 1);       // %1024
    const int tid = threadIdx.x;
    const int warp = tid >> 5;
    const int lane = tid & 31;

    // Base pointer for this (b,v): element offset b*S*V*D + v*D, in float2 units.
    const size_t base_f2   = ((size_t)b * SS * VV * DD + (size_t)v * DD) >> 1;
    const size_t srow_f2   = ((size_t)VV * DD) >> 1;     // stride between s rows
    const float2* __restrict__ xp = reinterpret_cast<const float2*>(x) + base_f2 + tid;

    // Per-thread slice of w_eff (constant across s): one read each.
    const float w0 = g_weff[2 * tid];
    const float w1 = g_weff[2 * tid + 1];
    const float cbias = g_c;

    __shared__ float red[2][8][4];   // [buffer][warp][j] partial dot sums

    float acc0 = 0.0f, acc1 = 0.0f;  // running weighted x accumulators
    float m = -INFINITY;             // running max
    float l = 0.0f;                  // running sum of exp

#pragma unroll 1
    for (int c = 0; c < SS / 4; ++c) {
        // ---- load 4 rows' slices (independent -> MLP=4) ----
        float2 xr0 = xp[(size_t)(4 * c + 0) * srow_f2];
        float2 xr1 = xp[(size_t)(4 * c + 1) * srow_f2];
        float2 xr2 = xp[(size_t)(4 * c + 2) * srow_f2];
        float2 xr3 = xp[(size_t)(4 * c + 3) * srow_f2];

        // ---- per-thread dot partials ----
        float p0 = xr0.x * w0 + xr0.y * w1;
        float p1 = xr1.x * w0 + xr1.y * w1;
        float p2 = xr2.x * w0 + xr2.y * w1;
        float p3 = xr3.x * w0 + xr3.y * w1;

        // ---- warp reduce (4 values) ----
#pragma unroll
        for (int off = 16; off > 0; off >>= 1) {
            p0 += __shfl_down_sync(0xffffffffu, p0, off);
            p1 += __shfl_down_sync(0xffffffffu, p1, off);
            p2 += __shfl_down_sync(0xffffffffu, p2, off);
            p3 += __shfl_down_sync(0xffffffffu, p3, off);
        }
        const int buf = c & 1;
        if (lane == 0) {
            red[buf][warp][0] = p0;
            red[buf][warp][1] = p1;
            red[buf][warp][2] = p2;
            red[buf][warp][3] = p3;
        }
        __syncthreads();

        // ---- every thread sums the 8 warp partials itself (broadcast reads) ----
        float sc0 = cbias, sc1 = cbias, sc2 = cbias, sc3 = cbias;
#pragma unroll
        for (int w = 0; w < 8; ++w) {
            sc0 += red[buf][w][0];
            sc1 += red[buf][w][1];
            sc2 += red[buf][w][2];
            sc3 += red[buf][w][3];
        }

        // ---- 4 sequential online-softmax updates (identical in all threads) ----
        float sc[4] = {sc0, sc1, sc2, sc3};
        float2 xr[4] = {xr0, xr1, xr2, xr3};
#pragma unroll
        for (int j = 0; j < 4; ++j) {
            float nm    = fmaxf(m, sc[j]);
            float alpha = __expf(m - nm);       // exp(-inf)=0 on first step
            float pj    = __expf(sc[j] - nm);
            l    = l * alpha + pj;
            acc0 = acc0 * alpha + pj * xr[j].x;
            acc1 = acc1 * alpha + pj * xr[j].y;
            m = nm;
        }
        // Buffer red[buf] is reused only at chunk c+2, after barrier(c+1): safe.
    }

    const float inv = 1.0f / l;
    float2 o;
    o.x = acc0 * inv;
    o.y = acc1 * inv;
    // out[b, v, d] : [B, V, D]
    reinterpret_cast<float2*>(out)[(((size_t)b * VV + v) * DD >> 1) + tid] = o;
}

// ---------------------------------------------------------------------------
// Launch. Inputs (metadata order): x, W1, b1, W2, b2.
// ---------------------------------------------------------------------------
extern "C" void kernel_launch(void* const* d_in, const int* in_sizes, int n_in,
                              void* d_out, int out_size) {
    const float* x  = (const float*)d_in[0];
    const float* W1 = (const float*)d_in[1];
    const float* b1 = (const float*)d_in[2];
    const float* W2 = (const float*)d_in[3];
    const float* b2 = (const float*)d_in[4];
    float* out = (float*)d_out;

    weff_kernel<<<1, DD>>>(W1, b1, W2, b2);
    attn_kernel<<<BB * VV, 256>>>(x, out);
}

// round 3
// speedup vs baseline: 1.4611x; 1.4611x over previous
#include <cuda_runtime.h>
#include <math.h>

// Shapes fixed by the problem.
#define BB 2
#define SS 128
#define VV 1024
#define DD 512
#define KK 32

// Scratch for the collapsed first-layer weights (no device allocation allowed).
__device__ __align__(16) float g_weff[DD];
__device__ float g_c;

// ---------------------------------------------------------------------------
// Kernel 1: collapse the two linear layers.
//   w_eff[d] = sum_k W2[0,k] * W1[k,d];   c = b2[0] + sum_k b1[k]*W2[0,k]
// ---------------------------------------------------------------------------
__global__ void weff_kernel(const float* __restrict__ W1,
                            const float* __restrict__ b1,
                            const float* __restrict__ W2,
                            const float* __restrict__ b2) {
    int d = blockIdx.x * blockDim.x + threadIdx.x;
    if (d < DD) {
        float s = 0.0f;
#pragma unroll
        for (int k = 0; k < KK; ++k) s += W2[k] * W1[k * DD + d];
        g_weff[d] = s;
    }
    if (d == 0) {
        float c = b2[0];
#pragma unroll
        for (int k = 0; k < KK; ++k) c += b1[k] * W2[k];
        g_c = c;
    }
}

// ---------------------------------------------------------------------------
// Kernel 2: per-(b,v) online-softmax attention over S, single pass over x.
// One CTA per (b,v). 128 threads; thread t owns d = {4t..4t+3} (float4,
// LDG.128). Chunk of 8 s-rows: 8 loads -> 8 dot partials -> warp shuffle
// reduce -> vectorized cross-warp smem exchange (1 barrier, double-buffered)
// -> chunk-max deferred softmax (1 rescale + 8 exp per chunk).
// ---------------------------------------------------------------------------
__global__ __launch_bounds__(128, 8)
void attn_kernel(const float* __restrict__ x, float* __restrict__ out) {
    const int bv   = blockIdx.x;          // 0..2047
    const int b    = bv >> 10;
    const int v    = bv & (VV - 1);
    const int tid  = threadIdx.x;
    const int warp = tid >> 5;
    const int lane = tid & 31;

    const size_t base_f4 = ((size_t)b * SS * VV * DD + (size_t)v * DD) >> 2;
    const size_t srow_f4 = ((size_t)VV * DD) >> 2;   // float4 stride between s rows
    const float4* __restrict__ xp =
        reinterpret_cast<const float4*>(x) + base_f4 + tid;

    const float4 w = reinterpret_cast<const float4*>(g_weff)[tid];
    const float cbias = g_c;

    __shared__ float4 red[2][4][2];   // [buffer][warp][half]: 8 partial dots/warp

    float4 acc = make_float4(0.f, 0.f, 0.f, 0.f);
    float m = -INFINITY;
    float l = 0.0f;

#pragma unroll 1
    for (int c = 0; c < SS / 8; ++c) {
        // ---- 8 independent LDG.128 (MLP=8) ----
        float4 xr[8];
#pragma unroll
        for (int j = 0; j < 8; ++j)
            xr[j] = xp[(size_t)(8 * c + j) * srow_f4];

        // ---- per-thread dot partials ----
        float p[8];
#pragma unroll
        for (int j = 0; j < 8; ++j)
            p[j] = xr[j].x * w.x + xr[j].y * w.y + xr[j].z * w.z + xr[j].w * w.w;

        // ---- warp reduce (8 values) ----
#pragma unroll
        for (int off = 16; off > 0; off >>= 1) {
#pragma unroll
            for (int j = 0; j < 8; ++j)
                p[j] += __shfl_down_sync(0xffffffffu, p[j], off);
        }

        const int buf = c & 1;
        if (lane == 0) {
            red[buf][warp][0] = make_float4(p[0], p[1], p[2], p[3]);
            red[buf][warp][1] = make_float4(p[4], p[5], p[6], p[7]);
        }
        __syncthreads();

        // ---- every thread sums the 4 warp partials (8 LDS.128, broadcast) ----
        float sc[8];
#pragma unroll
        for (int j = 0; j < 8; ++j) sc[j] = cbias;
#pragma unroll
        for (int wi = 0; wi < 4; ++wi) {
            float4 a = red[buf][wi][0];
            float4 bq = red[buf][wi][1];
            sc[0] += a.x;  sc[1] += a.y;  sc[2] += a.z;  sc[3] += a.w;
            sc[4] += bq.x; sc[5] += bq.y; sc[6] += bq.z; sc[7] += bq.w;
        }

        // ---- chunk-deferred online softmax: 1 rescale + 8 exp ----
        float cm = sc[0];
#pragma unroll
        for (int j = 1; j < 8; ++j) cm = fmaxf(cm, sc[j]);
        const float nm    = fmaxf(m, cm);
        const float alpha = __expf(m - nm);   // exp(-inf)=0 on first chunk
        m = nm;
        l *= alpha;
        acc.x *= alpha; acc.y *= alpha; acc.z *= alpha; acc.w *= alpha;
#pragma unroll
        for (int j = 0; j < 8; ++j) {
            const float pj = __expf(sc[j] - nm);
            l += pj;
            acc.x += pj * xr[j].x;
            acc.y += pj * xr[j].y;
            acc.z += pj * xr[j].z;
            acc.w += pj * xr[j].w;
        }
        // red[buf] is next written at chunk c+2, which is after barrier(c+1);
        // all reads of red[buf] complete before barrier(c+1): safe.
    }

    const float inv = 1.0f / l;
    float4 o = make_float4(acc.x * inv, acc.y * inv, acc.z * inv, acc.w * inv);
    reinterpret_cast<float4*>(out)[(((size_t)b * VV + v) * DD >> 2) + tid] = o;
}

// ---------------------------------------------------------------------------
// Launch. Inputs (metadata order): x, W1, b1, W2, b2.
// ---------------------------------------------------------------------------
extern "C" void kernel_launch(void* const* d_in, const int* in_sizes, int n_in,
                              void* d_out, int out_size) {
    const float* x  = (const float*)d_in[0];
    const float* W1 = (const float*)d_in[1];
    const float* b1 = (const float*)d_in[2];
    const float* W2 = (const float*)d_in[3];
    const float* b2 = (const float*)d_in[4];
    float* out = (float*)d_out;

    weff_kernel<<<1, DD>>>(W1, b1, W2, b2);
    attn_kernel<<<BB * VV, 128>>>(x, out);
}